// round 4
// baseline (speedup 1.0000x reference)
#include <cuda_runtime.h>

// Problem shape (fixed by the dataset)
#define BB   2
#define NN   20000
#define KK   16
#define CIN  128
#define MM   9
#define COUT 128
#define MP   16                 // padded stride for xu rows (sector aligned)
#define NROWS (BB*NN)           // 40000 flattened (b,n)
#define KDIM  (MM*CIN)          // 1152 contraction dim of the big GEMM

// Scratch (device globals: allocation-free per harness rules)
__device__ float g_xu[(size_t)NROWS * MP];        // 2.56 MB: xu[b,n,m] = x[b,n]·u[m]
__device__ float g_Y [(size_t)NROWS * KDIM];      // 184 MB:  Y[n, m*128+c]
__device__ float g_WT[KDIM * COUT];               // 589 KB:  WT[m*128+c][o] = W[m][o][c]

// ---- packed f32x2 helpers (Blackwell FFMA2 path) -------------------------
__device__ __forceinline__ unsigned long long pk2(float lo, float hi){
    unsigned long long r;
    asm("mov.b64 %0, {%1, %2};" : "=l"(r) : "f"(lo), "f"(hi));
    return r;
}
__device__ __forceinline__ void fma2(unsigned long long& d,
                                     unsigned long long a, unsigned long long b){
    asm("fma.rn.f32x2 %0, %1, %2, %0;" : "+l"(d) : "l"(a), "l"(b));
}
__device__ __forceinline__ float2 up2(unsigned long long v){
    float lo, hi;
    asm("mov.b64 {%0, %1}, %2;" : "=f"(lo), "=f"(hi) : "l"(v));
    return make_float2(lo, hi);
}

// ---- Kernel A: xu[b,n,m] = dot(x[b,n,:], u[m,:]) -------------------------
// One warp per node; lanes split C into float4 chunks, butterfly-reduce.
__global__ void xu_kernel(const float* __restrict__ x, const float* __restrict__ u){
    __shared__ float su[MM*CIN];
    for (int i = threadIdx.x; i < MM*CIN; i += blockDim.x) su[i] = u[i];
    __syncthreads();
    int gw  = (blockIdx.x * blockDim.x + threadIdx.x) >> 5;
    int lid = threadIdx.x & 31;
    if (gw >= NROWS) return;
    float4 xv = *(const float4*)(x + (size_t)gw*CIN + lid*4);
    float p[MM];
    #pragma unroll
    for (int m = 0; m < MM; ++m){
        float4 uv = *(const float4*)(su + m*CIN + lid*4);
        p[m] = xv.x*uv.x + xv.y*uv.y + xv.z*uv.z + xv.w*uv.w;
    }
    #pragma unroll
    for (int off = 16; off; off >>= 1)
        #pragma unroll
        for (int m = 0; m < MM; ++m)
            p[m] += __shfl_xor_sync(0xffffffffu, p[m], off);
    if (lid == 0){
        float* dst = g_xu + (size_t)gw*MP;
        #pragma unroll
        for (int m = 0; m < MM; ++m) dst[m] = p[m];
    }
}

// ---- Kernel B: transpose W[m][o][c] -> WT[m*128+c][o] --------------------
__global__ void wt_kernel(const float* __restrict__ W){
    int idx = blockIdx.x*blockDim.x + threadIdx.x;
    if (idx >= MM*COUT*CIN) return;
    int c = idx % CIN;
    int o = (idx / CIN) % COUT;
    int m = idx / (CIN*COUT);
    g_WT[(m*CIN + c)*COUT + o] = W[idx];
}

// ---- Kernel C: per-node softmax q (deg_inv folded in) + Y materialize ----
// One warp per node. Lane k<16 computes q[k][0..8]; all lanes then build
// Y[m][c] = sum_k q'[k][m] * patch[k][c] with each lane owning 4 channels.
#define QY_WARPS 8
__global__ void qy_kernel(const float* __restrict__ x, const int* __restrict__ adj,
                          const float* __restrict__ cb){
    __shared__ float qs[QY_WARPS][KK][MM];
    int lid  = threadIdx.x & 31;
    int w    = threadIdx.x >> 5;
    int node = blockIdx.x * QY_WARPS + w;
    if (node >= NROWS) return;
    int b = node / NN;
    int n = node - b*NN;

    int j = 0;
    if (lid < KK) j = adj[n*KK + lid];
    unsigned nz = __ballot_sync(0xffffffffu, j != 0);
    int   deg  = __popc(nz);
    float dinv = (deg > 0) ? (1.0f / (float)deg) : 0.0f;

    if (lid < KK){
        if (j != 0){
            const float* xs = g_xu + (size_t)node * MP;
            const float* xp = g_xu + (size_t)(b*NN + (j-1)) * MP;
            float lg[MM]; float mx = -1e30f;
            #pragma unroll
            for (int m = 0; m < MM; ++m){
                lg[m] = xs[m] - xp[m] + cb[m];
                mx = fmaxf(mx, lg[m]);
            }
            float s = 0.f;
            #pragma unroll
            for (int m = 0; m < MM; ++m){ lg[m] = __expf(lg[m] - mx); s += lg[m]; }
            float r = dinv / s;                       // softmax * deg_inv fused
            #pragma unroll
            for (int m = 0; m < MM; ++m) qs[w][lid][m] = lg[m] * r;
        } else {
            #pragma unroll
            for (int m = 0; m < MM; ++m) qs[w][lid][m] = 0.f;
        }
    }
    __syncwarp();

    unsigned long long acc[MM][2];
    #pragma unroll
    for (int m = 0; m < MM; ++m){ acc[m][0] = 0ull; acc[m][1] = 0ull; }

    #pragma unroll
    for (int k = 0; k < KK; ++k){
        int jk = __shfl_sync(0xffffffffu, j, k);
        if (jk == 0) continue;                        // zero patch contributes nothing
        float4 p = *(const float4*)(x + (size_t)(b*NN + (jk-1))*CIN + lid*4);
        unsigned long long p0 = pk2(p.x, p.y), p1 = pk2(p.z, p.w);
        #pragma unroll
        for (int m = 0; m < MM; ++m){
            float qv = qs[w][k][m];
            unsigned long long q2 = pk2(qv, qv);
            fma2(acc[m][0], q2, p0);
            fma2(acc[m][1], q2, p1);
        }
    }
    #pragma unroll
    for (int m = 0; m < MM; ++m){
        float2 a = up2(acc[m][0]);
        float2 c2 = up2(acc[m][1]);
        *(float4*)(g_Y + (size_t)node*KDIM + m*CIN + lid*4) =
            make_float4(a.x, a.y, c2.x, c2.y);
    }
}

// ---- Kernel D: out[r][o] = Y[r][:] · WT[:][o] + bias[o] ------------------
// Tiled fp32 GEMM with packed FFMA2: BM=128, BN=64, BK=16, 256 threads,
// each thread computes an 8x4 micro-tile (stored as 4x4 f32x2 row pairs).
#define BM 128
#define BN 64
#define BKT 16
#define ASTRIDE 132   // padded to cut transposed-store bank conflicts, 16B-aligned rows

__global__ void __launch_bounds__(256)
gemm_kernel(const float* __restrict__ bias, float* __restrict__ out){
    __shared__ float As[BKT*ASTRIDE];   // As[kk][row]
    __shared__ float Bs[BKT*BN];        // Bs[kk][o]
    int tid = threadIdx.x;
    int tx  = tid & 15;                 // col group -> cols tx*4 .. +3
    int ty  = tid >> 4;                 // row group -> rows ty*8 .. +7
    int row0 = blockIdx.x * BM;
    int col0 = blockIdx.y * BN;

    int arow = tid >> 2;                // 0..63 (second half via s=1)
    int akk  = (tid & 3) * 4;           // kk base 0/4/8/12
    int bkk  = tid >> 4;                // 0..15
    int bc   = (tid & 15) * 4;

    unsigned long long acc[4][4];
    #pragma unroll
    for (int i = 0; i < 4; ++i)
        #pragma unroll
        for (int jj = 0; jj < 4; ++jj) acc[i][jj] = 0ull;

    float4 pa[2], pb;
    {   // prefetch tile 0
        #pragma unroll
        for (int s = 0; s < 2; ++s){
            int r = row0 + arow + s*64;
            pa[s] = (r < NROWS) ? *(const float4*)(g_Y + (size_t)r*KDIM + akk)
                                : make_float4(0.f,0.f,0.f,0.f);
        }
        pb = *(const float4*)(g_WT + (size_t)bkk*COUT + col0 + bc);
    }

    const int NT = KDIM / BKT;          // 72
    for (int t = 0; t < NT; ++t){
        __syncthreads();
        #pragma unroll
        for (int s = 0; s < 2; ++s){
            int r = arow + s*64;
            As[(akk+0)*ASTRIDE + r] = pa[s].x;
            As[(akk+1)*ASTRIDE + r] = pa[s].y;
            As[(akk+2)*ASTRIDE + r] = pa[s].z;
            As[(akk+3)*ASTRIDE + r] = pa[s].w;
        }
        *(float4*)(Bs + bkk*BN + bc) = pb;
        __syncthreads();

        if (t + 1 < NT){                // prefetch next tile while computing
            int k0 = (t+1)*BKT;
            #pragma unroll
            for (int s = 0; s < 2; ++s){
                int r = row0 + arow + s*64;
                pa[s] = (r < NROWS) ? *(const float4*)(g_Y + (size_t)r*KDIM + k0 + akk)
                                    : make_float4(0.f,0.f,0.f,0.f);
            }
            pb = *(const float4*)(g_WT + (size_t)(k0 + bkk)*COUT + col0 + bc);
        }

        #pragma unroll
        for (int kk = 0; kk < BKT; ++kk){
            float4 a0 = *(const float4*)(As + kk*ASTRIDE + ty*8);
            float4 a1 = *(const float4*)(As + kk*ASTRIDE + ty*8 + 4);
            float4 bv = *(const float4*)(Bs + kk*BN + tx*4);
            unsigned long long ap[4] = { pk2(a0.x,a0.y), pk2(a0.z,a0.w),
                                         pk2(a1.x,a1.y), pk2(a1.z,a1.w) };
            unsigned long long bd[4] = { pk2(bv.x,bv.x), pk2(bv.y,bv.y),
                                         pk2(bv.z,bv.z), pk2(bv.w,bv.w) };
            #pragma unroll
            for (int i = 0; i < 4; ++i)
                #pragma unroll
                for (int jj = 0; jj < 4; ++jj)
                    fma2(acc[i][jj], ap[i], bd[jj]);
        }
    }

    float4 bvec = *(const float4*)(bias + col0 + tx*4);
    #pragma unroll
    for (int i = 0; i < 4; ++i){
        float2 c0 = up2(acc[i][0]);
        float2 c1 = up2(acc[i][1]);
        float2 c2 = up2(acc[i][2]);
        float2 c3 = up2(acc[i][3]);
        int r = row0 + ty*8 + i*2;
        if (r < NROWS)
            *(float4*)(out + (size_t)r*COUT + col0 + tx*4) =
                make_float4(c0.x+bvec.x, c1.x+bvec.y, c2.x+bvec.z, c3.x+bvec.w);
        if (r + 1 < NROWS)
            *(float4*)(out + (size_t)(r+1)*COUT + col0 + tx*4) =
                make_float4(c0.y+bvec.x, c1.y+bvec.y, c2.y+bvec.z, c3.y+bvec.w);
    }
}

extern "C" void kernel_launch(void* const* d_in, const int* in_sizes, int n_in,
                              void* d_out, int out_size){
    const float* x    = (const float*)d_in[0];   // (2,20000,128) f32
    const int*   adj  = (const int*)  d_in[1];   // (20000,16)    i32
    const float* W    = (const float*)d_in[2];   // (9,128,128)   f32
    const float* bias = (const float*)d_in[3];   // (128,)        f32
    const float* u    = (const float*)d_in[4];   // (9,128)       f32
    const float* cb   = (const float*)d_in[5];   // (9,)          f32
    float* out = (float*)d_out;                  // (2,20000,128) f32

    // A: xu precompute — 40000 warps
    xu_kernel<<<NROWS/8, 256>>>(x, u);
    // B: W transpose (independent of A, stream-serialized is fine)
    wt_kernel<<<(MM*COUT*CIN + 255)/256, 256>>>(W);
    // C: softmax q (+deg_inv fold) and Y materialization — 40000 warps
    qy_kernel<<<NROWS/QY_WARPS, 256>>>(x, adj, cb);
    // D: GEMM [40000 x 1152] x [1152 x 128] + bias
    dim3 g2((NROWS + BM - 1)/BM, COUT/BN);       // 313 x 2
    gemm_kernel<<<g2, 256>>>(bias, out);
}

// round 7
// speedup vs baseline: 1.4431x; 1.4431x over previous
#include <cuda_runtime.h>
#include <cstdint>

// Problem shape (fixed by the dataset)
#define BB   2
#define NN   20000
#define KK   16
#define CIN  128
#define MM   9
#define COUT 128
#define MP   16
#define NROWS (BB*NN)           // 40000
#define KDIM  (MM*CIN)          // 1152

// Scratch (device globals: allocation-free per harness rules)
__device__ float g_xu[(size_t)NROWS * MP];        // 2.56 MB
__device__ float g_Y [(size_t)NROWS * KDIM];      // 184 MB  (tf32-rounded fp32)
__device__ float g_WT[KDIM * COUT];               // 589 KB  WT[m*128+c][o], tf32-rounded

// ---- packed f32x2 helpers (for qy inner product) -------------------------
__device__ __forceinline__ unsigned long long pk2(float lo, float hi){
    unsigned long long r;
    asm("mov.b64 %0, {%1, %2};" : "=l"(r) : "f"(lo), "f"(hi));
    return r;
}
__device__ __forceinline__ void fma2(unsigned long long& d,
                                     unsigned long long a, unsigned long long b){
    asm("fma.rn.f32x2 %0, %1, %2, %0;" : "+l"(d) : "l"(a), "l"(b));
}
__device__ __forceinline__ float2 up2(unsigned long long v){
    float lo, hi;
    asm("mov.b64 {%0, %1}, %2;" : "=f"(lo), "=f"(hi) : "l"(v));
    return make_float2(lo, hi);
}
__device__ __forceinline__ float tf32r(float v){     // round-to-nearest tf32
    uint32_t r; asm("cvt.rna.tf32.f32 %0, %1;" : "=r"(r) : "f"(v));
    return __uint_as_float(r);
}
__device__ __forceinline__ uint32_t smem_u32(const void* p){
    uint32_t a;
    asm("{ .reg .u64 t; cvta.to.shared.u64 t, %1; cvt.u32.u64 %0, t; }" : "=r"(a) : "l"(p));
    return a;
}
__device__ __forceinline__ void cpasync16(uint32_t dst, const void* src, bool pred){
    int sz = pred ? 16 : 0;
    asm volatile("cp.async.cg.shared.global [%0], [%1], 16, %2;"
                 :: "r"(dst), "l"(src), "r"(sz) : "memory");
}

// ---- Kernel A: xu[b,n,m] = dot(x[b,n,:], u[m,:]) -------------------------
__global__ void xu_kernel(const float* __restrict__ x, const float* __restrict__ u){
    __shared__ float su[MM*CIN];
    for (int i = threadIdx.x; i < MM*CIN; i += blockDim.x) su[i] = u[i];
    __syncthreads();
    int gw  = (blockIdx.x * blockDim.x + threadIdx.x) >> 5;
    int lid = threadIdx.x & 31;
    if (gw >= NROWS) return;
    float4 xv = *(const float4*)(x + (size_t)gw*CIN + lid*4);
    float p[MM];
    #pragma unroll
    for (int m = 0; m < MM; ++m){
        float4 uv = *(const float4*)(su + m*CIN + lid*4);
        p[m] = xv.x*uv.x + xv.y*uv.y + xv.z*uv.z + xv.w*uv.w;
    }
    #pragma unroll
    for (int off = 16; off; off >>= 1)
        #pragma unroll
        for (int m = 0; m < MM; ++m)
            p[m] += __shfl_xor_sync(0xffffffffu, p[m], off);
    if (lid == 0){
        float* dst = g_xu + (size_t)gw*MP;
        #pragma unroll
        for (int m = 0; m < MM; ++m) dst[m] = p[m];
    }
}

// ---- Kernel B: W[m][o][c] -> WT[m*128+c][o], tf32-rounded ----------------
__global__ void wt_kernel(const float* __restrict__ W){
    int idx = blockIdx.x*blockDim.x + threadIdx.x;
    if (idx >= MM*COUT*CIN) return;
    int c = idx % CIN;
    int o = (idx / CIN) % COUT;
    int m = idx / (CIN*COUT);
    g_WT[(m*CIN + c)*COUT + o] = tf32r(W[idx]);
}

// ---- Kernel C: softmax q (deg_inv folded) + Y materialize (tf32-rounded) -
#define QY_WARPS 8
__global__ void qy_kernel(const float* __restrict__ x, const int* __restrict__ adj,
                          const float* __restrict__ cb){
    __shared__ float qs[QY_WARPS][KK][MM];
    int lid  = threadIdx.x & 31;
    int w    = threadIdx.x >> 5;
    int node = blockIdx.x * QY_WARPS + w;
    if (node >= NROWS) return;
    int b = node / NN;
    int n = node - b*NN;

    int j = 0;
    if (lid < KK) j = adj[n*KK + lid];
    unsigned nz = __ballot_sync(0xffffffffu, j != 0);
    int   deg  = __popc(nz);
    float dinv = (deg > 0) ? (1.0f / (float)deg) : 0.0f;

    if (lid < KK){
        if (j != 0){
            const float* xs = g_xu + (size_t)node * MP;
            const float* xp = g_xu + (size_t)(b*NN + (j-1)) * MP;
            float lg[MM]; float mx = -1e30f;
            #pragma unroll
            for (int m = 0; m < MM; ++m){
                lg[m] = xs[m] - xp[m] + cb[m];
                mx = fmaxf(mx, lg[m]);
            }
            float s = 0.f;
            #pragma unroll
            for (int m = 0; m < MM; ++m){ lg[m] = __expf(lg[m] - mx); s += lg[m]; }
            float r = dinv / s;
            #pragma unroll
            for (int m = 0; m < MM; ++m) qs[w][lid][m] = lg[m] * r;
        } else {
            #pragma unroll
            for (int m = 0; m < MM; ++m) qs[w][lid][m] = 0.f;
        }
    }
    __syncwarp();

    unsigned long long acc[MM][2];
    #pragma unroll
    for (int m = 0; m < MM; ++m){ acc[m][0] = 0ull; acc[m][1] = 0ull; }

    #pragma unroll
    for (int k = 0; k < KK; ++k){
        int jk = __shfl_sync(0xffffffffu, j, k);
        if (jk == 0) continue;
        float4 p = *(const float4*)(x + (size_t)(b*NN + (jk-1))*CIN + lid*4);
        unsigned long long p0 = pk2(p.x, p.y), p1 = pk2(p.z, p.w);
        #pragma unroll
        for (int m = 0; m < MM; ++m){
            float qv = qs[w][k][m];
            unsigned long long q2 = pk2(qv, qv);
            fma2(acc[m][0], q2, p0);
            fma2(acc[m][1], q2, p1);
        }
    }
    #pragma unroll
    for (int m = 0; m < MM; ++m){
        float2 a  = up2(acc[m][0]);
        float2 c2 = up2(acc[m][1]);
        *(float4*)(g_Y + (size_t)node*KDIM + m*CIN + lid*4) =
            make_float4(tf32r(a.x), tf32r(a.y), tf32r(c2.x), tf32r(c2.y));
    }
}

// ---- Kernel D: tf32 mma.sync GEMM  out = Y x WT + bias -------------------
// BM=128, BN=128(=COUT), BK=16, 128 threads (4 warps, warp tile 64x64),
// 2-stage cp.async pipeline. Smem padded for conflict-free fragment loads.
#define BMg 128
#define BNg 128
#define BKg 16
#define ASTR 20    // BK+4: bank = (20*g + tig) % 32 -> all 32 distinct
#define BSTR 136   // BN+8: bank = (8*tig + g) % 32 -> all 32 distinct
#define NTg (KDIM/BKg)   // 72

__global__ void __launch_bounds__(128)
gemm_kernel(const float* __restrict__ bias, float* __restrict__ out){
    __shared__ float As[2][BMg][ASTR];   // 20.5 KB
    __shared__ float Bs[2][BKg][BSTR];   // 17.4 KB
    int tid  = threadIdx.x;
    int lane = tid & 31, wid = tid >> 5;
    int warpM = wid >> 1, warpN = wid & 1;
    int g = lane >> 2, tig = lane & 3;
    int row0 = blockIdx.x * BMg;

    // loader mappings
    bool arow_ok = (row0 + tid) < NROWS;
    const float* Abase = g_Y + (size_t)(arow_ok ? (row0 + tid) : 0) * KDIM;
    int bkr = tid >> 3;                 // 0..15
    int bcb = (tid & 7) * 16;           // 0,16,...,112
    uint32_t aSm[2], bSm[2];
    aSm[0] = smem_u32(&As[0][tid][0]);  aSm[1] = smem_u32(&As[1][tid][0]);
    bSm[0] = smem_u32(&Bs[0][bkr][bcb]); bSm[1] = smem_u32(&Bs[1][bkr][bcb]);

    float acc[4][8][4];
    #pragma unroll
    for (int mt = 0; mt < 4; ++mt)
        #pragma unroll
        for (int nt = 0; nt < 8; ++nt)
            #pragma unroll
            for (int i = 0; i < 4; ++i) acc[mt][nt][i] = 0.f;

    // prologue: stage 0
    {
        const float* bsrc = g_WT + (size_t)bkr*COUT + bcb;
        #pragma unroll
        for (int c = 0; c < 4; ++c){
            cpasync16(aSm[0] + c*16, Abase + c*4, arow_ok);
            cpasync16(bSm[0] + c*16, bsrc + c*4, true);
        }
        asm volatile("cp.async.commit_group;" ::: "memory");
    }

    for (int t = 0; t < NTg; ++t){
        int s = t & 1;
        if (t + 1 < NTg){
            int kc = (t+1)*BKg, sn = (t+1) & 1;
            const float* bsrc = g_WT + (size_t)(kc + bkr)*COUT + bcb;
            #pragma unroll
            for (int c = 0; c < 4; ++c){
                cpasync16(aSm[sn] + c*16, Abase + kc + c*4, arow_ok);
                cpasync16(bSm[sn] + c*16, bsrc + c*4, true);
            }
            asm volatile("cp.async.commit_group;" ::: "memory");
            asm volatile("cp.async.wait_group 1;" ::: "memory");
        } else {
            asm volatile("cp.async.wait_group 0;" ::: "memory");
        }
        __syncthreads();

        #pragma unroll
        for (int ks = 0; ks < BKg; ks += 8){
            uint32_t af[4][4], bf[8][2];
            #pragma unroll
            for (int mt = 0; mt < 4; ++mt){
                int r = warpM*64 + mt*16 + g;
                af[mt][0] = __float_as_uint(As[s][r  ][ks+tig  ]);
                af[mt][1] = __float_as_uint(As[s][r+8][ks+tig  ]);
                af[mt][2] = __float_as_uint(As[s][r  ][ks+tig+4]);
                af[mt][3] = __float_as_uint(As[s][r+8][ks+tig+4]);
            }
            #pragma unroll
            for (int nt = 0; nt < 8; ++nt){
                int c = warpN*64 + nt*8 + g;
                bf[nt][0] = __float_as_uint(Bs[s][ks+tig  ][c]);
                bf[nt][1] = __float_as_uint(Bs[s][ks+tig+4][c]);
            }
            #pragma unroll
            for (int mt = 0; mt < 4; ++mt)
                #pragma unroll
                for (int nt = 0; nt < 8; ++nt)
                    asm volatile(
                        "mma.sync.aligned.m16n8k8.row.col.f32.tf32.tf32.f32 "
                        "{%0,%1,%2,%3}, {%4,%5,%6,%7}, {%8,%9}, {%0,%1,%2,%3};"
                        : "+f"(acc[mt][nt][0]), "+f"(acc[mt][nt][1]),
                          "+f"(acc[mt][nt][2]), "+f"(acc[mt][nt][3])
                        : "r"(af[mt][0]), "r"(af[mt][1]), "r"(af[mt][2]), "r"(af[mt][3]),
                          "r"(bf[nt][0]), "r"(bf[nt][1]));
        }
        __syncthreads();
    }

    // epilogue: bias + store
    float2 bv[8];
    #pragma unroll
    for (int nt = 0; nt < 8; ++nt){
        int c = warpN*64 + nt*8 + tig*2;
        bv[nt] = make_float2(__ldg(bias + c), __ldg(bias + c + 1));
    }
    #pragma unroll
    for (int mt = 0; mt < 4; ++mt){
        int r0 = row0 + warpM*64 + mt*16 + g;
        #pragma unroll
        for (int nt = 0; nt < 8; ++nt){
            int c = warpN*64 + nt*8 + tig*2;
            if (r0 < NROWS)
                *(float2*)(out + (size_t)r0*COUT + c) =
                    make_float2(acc[mt][nt][0] + bv[nt].x, acc[mt][nt][1] + bv[nt].y);
            if (r0 + 8 < NROWS)
                *(float2*)(out + (size_t)(r0+8)*COUT + c) =
                    make_float2(acc[mt][nt][2] + bv[nt].x, acc[mt][nt][3] + bv[nt].y);
        }
    }
}

extern "C" void kernel_launch(void* const* d_in, const int* in_sizes, int n_in,
                              void* d_out, int out_size){
    const float* x    = (const float*)d_in[0];   // (2,20000,128) f32
    const int*   adj  = (const int*)  d_in[1];   // (20000,16)    i32
    const float* W    = (const float*)d_in[2];   // (9,128,128)   f32
    const float* bias = (const float*)d_in[3];   // (128,)        f32
    const float* u    = (const float*)d_in[4];   // (9,128)       f32
    const float* cb   = (const float*)d_in[5];   // (9,)          f32
    float* out = (float*)d_out;                  // (2,20000,128) f32

    xu_kernel<<<NROWS/8, 256>>>(x, u);
    wt_kernel<<<(MM*COUT*CIN + 255)/256, 256>>>(W);
    qy_kernel<<<NROWS/QY_WARPS, 256>>>(x, adj, cb);
    gemm_kernel<<<(NROWS + BMg - 1)/BMg, 128>>>(bias, out);
}